// round 8
// baseline (speedup 1.0000x reference)
#include <cuda_runtime.h>
#include <cstdint>

#define NC      100000
#define FEAT    256
#define BATCH   16384
#define F4      64                       // FEAT / 4
#define THREADS 256
#define WPB     8
#define GRID    592                      // 148 SMs x 4 CTAs: co-resident by construction
#define NWARP   (GRID * WPB)             // 4736
#define CPB     256
#define NCHUNK  ((NC + CPB - 1) / CPB)   // 391  (< GRID: one chunk per CTA)

// contrib_c = Q - 1.9602 D + 0.9801 E - (0.0199/n) ||s||^2
//   Q = sum ||x_i||^2, D = c.s, E = n ||c||^2   (t = 0.99c + 0.01 s/n)
#define A_D 1.9602f
#define A_E 0.9801f
#define A_S 0.0199f

// Scratch — zero at module load; every replay restores the all-zero invariant.
__device__ float4   g_scal[NC];                 // {Q, D, E, n}  (1.6 MB)
__device__ float4   g_sums[(size_t)NC * F4];    // rows used ONLY for n>=2 classes
__device__ float    g_loss;
__device__ unsigned g_done;
__device__ unsigned g_bar[2];

__device__ __forceinline__ void red_add_v4(float* addr, float4 v) {
    asm volatile("red.global.add.v4.f32 [%0], {%1, %2, %3, %4};"
                 :: "l"(addr), "f"(v.x), "f"(v.y), "f"(v.z), "f"(v.w)
                 : "memory");
}
__device__ __forceinline__ float dot4(float4 a, float4 b) {
    return a.x*b.x + a.y*b.y + a.z*b.z + a.w*b.w;
}

// Grid-wide barrier: safe because all GRID CTAs are co-resident.
__device__ __forceinline__ void grid_barrier(unsigned* ctr) {
    __syncthreads();
    if (threadIdx.x == 0) {
        __threadfence();                                   // publish phase writes
        asm volatile("red.global.add.u32 [%0], 1;" :: "l"(ctr) : "memory");
        volatile unsigned* v = ctr;
        while (*v < GRID) { }
        __threadfence();                                   // acquire
    }
    __syncthreads();
}

__global__ __launch_bounds__(THREADS, 4)
void fused(const float* __restrict__ x, const float* __restrict__ center,
           const int* __restrict__ label, float* __restrict__ out) {
    int tid  = threadIdx.x;
    int lane = tid & 31;
    int wid  = tid >> 5;

    // ---------------- Phase 1: per-class counts (grid-stride) ----------------
    for (int i = blockIdx.x * THREADS + tid; i < BATCH; i += GRID * THREADS)
        atomicAdd(&g_scal[label[i]].w, 1.0f);

    grid_barrier(&g_bar[0]);

    // ---------------- Phase 2: warp-per-sample accumulate --------------------
    for (int s = blockIdx.x * WPB + wid; s < BATCH; s += NWARP) {
        int c = label[s];                                  // broadcast load
        const float4* xr = reinterpret_cast<const float4*>(x)      + (size_t)s * F4;
        const float4* cr = reinterpret_cast<const float4*>(center) + (size_t)c * F4;
        float4 v0 = xr[lane], v1 = xr[lane + 32];
        float4 c0 = cr[lane], c1 = cr[lane + 32];

        float q = dot4(v0, v0) + dot4(v1, v1);
        float d = dot4(v0, c0) + dot4(v1, c1);
        float e = dot4(c0, c0) + dot4(c1, c1);
        #pragma unroll
        for (int o = 16; o > 0; o >>= 1) {
            q += __shfl_down_sync(0xFFFFFFFFu, q, o);
            d += __shfl_down_sync(0xFFFFFFFFu, d, o);
            e += __shfl_down_sync(0xFFFFFFFFu, e, o);
        }

        if (g_scal[c].w >= 2.f) {                          // multi class: need s vector
            float* srow = reinterpret_cast<float*>(g_sums + (size_t)c * F4);
            red_add_v4(srow + lane * 4,        v0);
            red_add_v4(srow + (lane + 32) * 4, v1);
        }
        if (lane == 0) {
            atomicAdd(&g_scal[c].x, q);
            atomicAdd(&g_scal[c].y, d);
            atomicAdd(&g_scal[c].z, e);
        }
    }

    grid_barrier(&g_bar[1]);

    // ---------------- Phase 3: one 256-class chunk per CTA -------------------
    __shared__ int   s_m;
    __shared__ int   s_cls[CPB];
    __shared__ float s_n[CPB];
    __shared__ float s_wsum[WPB];

    if (tid == 0) s_m = 0;
    __syncthreads();

    float contrib = 0.f;
    if (blockIdx.x < NCHUNK) {
        int c = blockIdx.x * CPB + tid;
        if (c < NC) {
            float4 sc = g_scal[c];                         // coalesced 16B
            if (sc.w > 0.f) {
                contrib = sc.x - A_D * sc.y + A_E * sc.z;
                if (sc.w == 1.f) {
                    contrib -= A_S * sc.x;                 // ||s||^2 == Q for n = 1
                } else {
                    int p = atomicAdd(&s_m, 1);
                    s_cls[p] = c;
                    s_n[p]   = sc.w;
                }
                g_scal[c] = make_float4(0.f, 0.f, 0.f, 0.f);  // restore invariant
            }
        }
    }
    __syncthreads();

    int m = s_m;                                           // ~3 multi classes/chunk
    for (int i = wid; i < m; i += WPB) {
        int cc = s_cls[i];
        float4* srow = g_sums + (size_t)cc * F4;
        float4 s0 = srow[lane], s1 = srow[lane + 32];
        float4 z = make_float4(0.f, 0.f, 0.f, 0.f);
        srow[lane] = z;                                    // restore invariant
        srow[lane + 32] = z;
        float ss = dot4(s0, s0) + dot4(s1, s1);
        #pragma unroll
        for (int o = 16; o > 0; o >>= 1)
            ss += __shfl_down_sync(0xFFFFFFFFu, ss, o);
        if (lane == 0) contrib -= A_S * ss / s_n[i];
    }

    #pragma unroll
    for (int o = 16; o > 0; o >>= 1)
        contrib += __shfl_down_sync(0xFFFFFFFFu, contrib, o);
    if (lane == 0) s_wsum[wid] = contrib;
    __syncthreads();

    if (tid == 0) {
        float b = 0.f;
        #pragma unroll
        for (int i = 0; i < WPB; i++) b += s_wsum[i];
        atomicAdd(&g_loss, b);                             // 592 ops, one addr: ~us-scale no
        __threadfence();
        if (atomicAdd(&g_done, 1u) == GRID - 1) {          // last CTA
            out[0] = __ldcg(&g_loss) * (1.f / ((float)BATCH * (float)FEAT));
            g_loss   = 0.f;                                // restore invariants
            g_done   = 0u;
            g_bar[0] = 0u;
            g_bar[1] = 0u;
        }
    }
}

extern "C" void kernel_launch(void* const* d_in, const int* in_sizes, int n_in,
                              void* d_out, int out_size) {
    const float* x      = (const float*)d_in[0];   // batch_feature [16384, 256] f32
    const int*   label  = (const int*)d_in[1];     // batch_label   [16384] int32
    const float* center = (const float*)d_in[2];   // center_feature[100000, 256] f32
    float* out = (float*)d_out;

    fused<<<GRID, THREADS>>>(x, center, label, out);
}

// round 9
// speedup vs baseline: 1.1363x; 1.1363x over previous
#include <cuda_runtime.h>
#include <cstdint>

#define NC         100000
#define FEAT       256
#define BATCH      16384
#define F4         64                          // FEAT / 4
#define THREADS    256
#define WPB        8
#define CNT_BLOCKS 128
#define ACC_BLOCKS (BATCH / WPB)               // 2048 (one warp per sample)
#define CPB        256                         // classes scanned per block
#define CLS_BLOCKS ((NC + CPB - 1) / CPB)      // 391

// contrib_c = Q - 1.9602 D + 0.9801 E - (0.0199/n) ||s||^2
//   Q = sum ||x_i||^2, D = c.s, E = n ||c||^2   (t = 0.99c + 0.01 s/n)
#define A_D 1.9602f
#define A_E 0.9801f
#define A_S 0.0199f

// Scratch — zero at module load; every replay restores the all-zero invariant.
__device__ float4   g_scal[NC];                 // {Q, D, E, n}  (1.6 MB)
__device__ float4   g_sums[(size_t)NC * F4];    // rows used ONLY for n>=2 classes
__device__ float    g_loss;
__device__ unsigned g_done;

__device__ __forceinline__ void red_add_v4(float* addr, float4 v) {
    asm volatile("red.global.add.v4.f32 [%0], {%1, %2, %3, %4};"
                 :: "l"(addr), "f"(v.x), "f"(v.y), "f"(v.z), "f"(v.w)
                 : "memory");
}
__device__ __forceinline__ void red_add_f32(float* addr, float v) {
    asm volatile("red.global.add.f32 [%0], %1;" :: "l"(addr), "f"(v) : "memory");
}
__device__ __forceinline__ float dot4(float4 a, float4 b) {
    return a.x*b.x + a.y*b.y + a.z*b.z + a.w*b.w;
}

// ---------------------------------------------------------------------------
// Pass 0: per-class counts (float, exact below 2^24). Spread REDs, tiny.
// ---------------------------------------------------------------------------
__global__ __launch_bounds__(THREADS) void countk(const int* __restrict__ label) {
    for (int i = blockIdx.x * THREADS + threadIdx.x; i < BATCH;
         i += CNT_BLOCKS * THREADS)
        red_add_f32(&g_scal[label[i]].w, 1.0f);
}

// ---------------------------------------------------------------------------
// Pass 1: one warp per sample. Read x row + gathered center row; warp-reduce
// Q, D, E -> scalar REDs (split across lanes 0/1/2); vector-RED the x row
// into g_sums only when the class is multi (n>=2).
// ---------------------------------------------------------------------------
__global__ __launch_bounds__(THREADS) void accum(const float* __restrict__ x,
                                                 const float* __restrict__ center,
                                                 const int* __restrict__ label) {
    int w    = (blockIdx.x * THREADS + threadIdx.x) >> 5;   // sample id
    int lane = threadIdx.x & 31;
    int c    = label[w];                                    // broadcast load

    float n = g_scal[c].w;          // issue early: overlaps with row loads below

    const float4* xr = reinterpret_cast<const float4*>(x)      + (size_t)w * F4;
    const float4* cr = reinterpret_cast<const float4*>(center) + (size_t)c * F4;
    float4 v0 = xr[lane], v1 = xr[lane + 32];
    float4 c0 = cr[lane], c1 = cr[lane + 32];

    float q = dot4(v0, v0) + dot4(v1, v1);
    float d = dot4(v0, c0) + dot4(v1, c1);
    float e = dot4(c0, c0) + dot4(c1, c1);
    #pragma unroll
    for (int o = 16; o > 0; o >>= 1) {
        q += __shfl_down_sync(0xFFFFFFFFu, q, o);
        d += __shfl_down_sync(0xFFFFFFFFu, d, o);
        e += __shfl_down_sync(0xFFFFFFFFu, e, o);
    }

    if (n >= 2.f) {                 // multi class: need the s vector
        float* srow = reinterpret_cast<float*>(g_sums + (size_t)c * F4);
        red_add_v4(srow + lane * 4,        v0);
        red_add_v4(srow + (lane + 32) * 4, v1);
    }

    // One RED instruction from lanes 0..2 instead of 3 serialized from lane 0.
    float qq = __shfl_sync(0xFFFFFFFFu, q, 0);
    float dd = __shfl_sync(0xFFFFFFFFu, d, 0);
    float ee = __shfl_sync(0xFFFFFFFFu, e, 0);
    if (lane < 3) {
        float  val  = (lane == 0) ? qq : (lane == 1) ? dd : ee;
        float* base = reinterpret_cast<float*>(&g_scal[c]);
        red_add_f32(base + lane, val);
    }
}

// ---------------------------------------------------------------------------
// Pass 2: coalesced scan of g_scal; multi classes (n>=2) get a warp stage for
// ||s||^2 + row zeroing. Block partial -> g_loss; last block writes out and
// resets. All zero invariants restored here.
// ---------------------------------------------------------------------------
__global__ __launch_bounds__(THREADS) void classpass(float* __restrict__ out) {
    __shared__ int   s_m;
    __shared__ int   s_cls[CPB];
    __shared__ float s_n[CPB];
    __shared__ float s_wsum[WPB];

    int tid  = threadIdx.x;
    int lane = tid & 31;
    int wid  = tid >> 5;

    if (tid == 0) s_m = 0;
    __syncthreads();

    float contrib = 0.f;
    int c = blockIdx.x * CPB + tid;
    if (c < NC) {
        float4 sc = g_scal[c];                  // coalesced 16B
        if (sc.w > 0.f) {
            contrib = sc.x - A_D * sc.y + A_E * sc.z;
            if (sc.w == 1.f) {
                contrib -= A_S * sc.x;          // ||s||^2 == Q for n = 1
            } else {
                int p = atomicAdd(&s_m, 1);
                s_cls[p] = c;
                s_n[p]   = sc.w;
            }
            g_scal[c] = make_float4(0.f, 0.f, 0.f, 0.f);    // restore invariant
        }
    }
    __syncthreads();

    int m = s_m;                                // ~3 multi classes per block
    for (int i = wid; i < m; i += WPB) {
        int cc = s_cls[i];
        float4* srow = g_sums + (size_t)cc * F4;
        float4 s0 = srow[lane], s1 = srow[lane + 32];
        float4 z = make_float4(0.f, 0.f, 0.f, 0.f);
        srow[lane] = z;                         // restore invariant
        srow[lane + 32] = z;
        float ss = dot4(s0, s0) + dot4(s1, s1);
        #pragma unroll
        for (int o = 16; o > 0; o >>= 1)
            ss += __shfl_down_sync(0xFFFFFFFFu, ss, o);
        if (lane == 0) contrib -= A_S * ss / s_n[i];
    }

    #pragma unroll
    for (int o = 16; o > 0; o >>= 1)
        contrib += __shfl_down_sync(0xFFFFFFFFu, contrib, o);
    if (lane == 0) s_wsum[wid] = contrib;
    __syncthreads();

    if (tid == 0) {
        float b = 0.f;
        #pragma unroll
        for (int i = 0; i < WPB; i++) b += s_wsum[i];
        atomicAdd(&g_loss, b);                  // 391 ops on one addr: ~0.3us
        __threadfence();
        if (atomicAdd(&g_done, 1u) == (unsigned)(gridDim.x - 1)) {
            out[0] = __ldcg(&g_loss) * (1.f / ((float)BATCH * (float)FEAT));
            g_loss = 0.f;                       // restore invariants
            g_done = 0u;
        }
    }
}

extern "C" void kernel_launch(void* const* d_in, const int* in_sizes, int n_in,
                              void* d_out, int out_size) {
    const float* x      = (const float*)d_in[0];   // batch_feature [16384, 256] f32
    const int*   label  = (const int*)d_in[1];     // batch_label   [16384] int32
    const float* center = (const float*)d_in[2];   // center_feature[100000, 256] f32
    float* out = (float*)d_out;

    countk   <<<CNT_BLOCKS, THREADS>>>(label);
    accum    <<<ACC_BLOCKS, THREADS>>>(x, center, label);
    classpass<<<CLS_BLOCKS, THREADS>>>(out);
}